// round 16
// baseline (speedup 1.0000x reference)
#include <cuda_runtime.h>
#include <math.h>

#define N_PTS 16384            // 2*8192 points, both batches flattened
#define KNN 5
#define NC 32                  // cells per axis (3D)
#define NCELLS (NC * NC * NC)  // 32768
#define XMIN (-4.5f)
#define XMAXV (4.5f)
#define W (9.0f / NC)          // 0.28125
#define INV_W (NC / 9.0f)

#define SUBW 2                                   // twin threads per source
#define MAIN_THREADS 128
#define SRC_PER_BLOCK (MAIN_THREADS / SUBW)      // 64
#define MAIN_BLOCKS (N_PTS / SRC_PER_BLOCK)      // 256

// ---- scratch (zero-initialized at module load; re-zeroed in-pipeline) ----
__device__ float4 g_tsort[N_PTS];   // (-2x,-2y,-2z,t^2) cell-ordered (linear z,y,x)
__device__ float4 g_ssort[N_PTS];   // (x,y,z, valid? s2 : -1) Morton-cell-ordered
__device__ int    g_thist[NCELLS];
__device__ int    g_shist[NCELLS];
__device__ int    g_tstart[NCELLS + 1];
__device__ int    g_tcur[NCELLS];
__device__ int    g_scur[NCELLS];
__device__ int    g_pubT[32], g_pubS[32];
__device__ int    g_flag[32];       // scan lookback flags (zeroed by finalize)
__device__ unsigned g_rowmask[NC];  // bit cy of word cz: target row (cz,cy) nonempty
__device__ float  g_bsum[MAIN_BLOCKS];
__device__ int    g_bcnt[MAIN_BLOCKS];

__device__ __forceinline__ int cell_coord(float v) {
    int c = (int)floorf((v - XMIN) * INV_W);
    return min(NC - 1, max(0, c));
}

__device__ __forceinline__ unsigned part1by2(unsigned v) {
    v &= 0x3FF;
    v = (v | (v << 16)) & 0x030000FF;
    v = (v | (v << 8))  & 0x0300F00F;
    v = (v | (v << 4))  & 0x030C30C3;
    v = (v | (v << 2))  & 0x09249249;
    return v;
}
__device__ __forceinline__ int morton3(int cx, int cy, int cz) {
    return (int)(part1by2(cx) | (part1by2(cy) << 1) | (part1by2(cz) << 2));
}

// ---------------------------------------------------------------------------
__global__ void hist_kernel(const float* __restrict__ src,
                            const float* __restrict__ tgt) {
    int gid = blockIdx.x * blockDim.x + threadIdx.x;   // 0..32767
    if (gid < N_PTS) {
        int cx = cell_coord(tgt[3 * gid]);
        int cy = cell_coord(tgt[3 * gid + 1]);
        int cz = cell_coord(tgt[3 * gid + 2]);
        atomicAdd(&g_thist[(cz * NC + cy) * NC + cx], 1);
    } else {
        int i = gid - N_PTS;
        int cx = cell_coord(src[3 * i]);
        int cy = cell_coord(src[3 * i + 1]);
        int cz = cell_coord(src[3 * i + 2]);
        atomicAdd(&g_shist[morton3(cx, cy, cz)], 1);
    }
}

// ---------------------------------------------------------------------------
// scan: ONE kernel, 32 co-resident blocks x 1024 threads, one cell/thread
// (coalesced). Block-local smem scan; cross-block offsets via publish +
// lookback spin. Emits tstart/tcur/scur + rowmask, re-zeroes histograms.
// ---------------------------------------------------------------------------
__global__ __launch_bounds__(1024) void scan_kernel() {
    __shared__ int pt[1024], ps[1024];
    __shared__ int vT[32], vS[32];
    __shared__ unsigned rowocc;
    const int tid = threadIdx.x, b = blockIdx.x;
    const int c = b * 1024 + tid;
    int tv = g_thist[c], sv = g_shist[c];
    if (tid == 0) rowocc = 0u;
    unsigned xbits = __ballot_sync(0xffffffffu, tv > 0);   // warp = one (z,y) row
    __syncthreads();
    if ((tid & 31) == 0 && xbits) atomicOr(&rowocc, 1u << (tid >> 5));
    pt[tid] = tv; ps[tid] = sv;
    __syncthreads();
    for (int off = 1; off < 1024; off <<= 1) {
        int ta = (tid >= off) ? pt[tid - off] : 0;
        int sa = (tid >= off) ? ps[tid - off] : 0;
        __syncthreads();
        pt[tid] += ta; ps[tid] += sa;
        __syncthreads();
    }
    if (tid == 1023) {
        g_pubT[b] = pt[1023];
        g_pubS[b] = ps[1023];
        __threadfence();
        *((volatile int*)&g_flag[b]) = 1;
        g_rowmask[b] = rowocc;          // block b == z-slab b
    }
    if (tid < 32) {
        int t = 0, s = 0;
        if (tid < b) {
            while (*((volatile int*)&g_flag[tid]) == 0) {}
            t = *((volatile int*)&g_pubT[tid]);
            s = *((volatile int*)&g_pubS[tid]);
        }
        vT[tid] = t; vS[tid] = s;
    }
    __syncthreads();
    int bofT = 0, bofS = 0;
    if (tid == 0) {
        for (int i = 0; i < 32; ++i) { bofT += vT[i]; bofS += vS[i]; }
        vT[0] = bofT; vS[0] = bofS;
    }
    __syncthreads();
    bofT = vT[0]; bofS = vS[0];
    int t = pt[tid] - tv + bofT;
    g_tstart[c] = t;  g_tcur[c] = t;
    g_scur[c] = ps[tid] - sv + bofS;
    g_thist[c] = 0;   g_shist[c] = 0;
    if (b == 31 && tid == 1023) g_tstart[NCELLS] = N_PTS;
}

// ---------------------------------------------------------------------------
__global__ void scatter_kernel(const float* __restrict__ src,
                               const float* __restrict__ tgt) {
    int gid = blockIdx.x * blockDim.x + threadIdx.x;
    if (gid < N_PTS) {
        float x = tgt[3 * gid], y = tgt[3 * gid + 1], z = tgt[3 * gid + 2];
        bool valid = (x != 0.0f) || (y != 0.0f) || (z != 0.0f);
        float t2 = fmaf(x, x, fmaf(y, y, z * z));
        float4 v;
        if (valid) { v.x = -2.0f * x; v.y = -2.0f * y; v.z = -2.0f * z; v.w = t2; }
        else       { v.x = 0.0f;      v.y = 0.0f;      v.z = 0.0f;      v.w = 1e30f; }
        int c = (cell_coord(z) * NC + cell_coord(y)) * NC + cell_coord(x);
        g_tsort[atomicAdd(&g_tcur[c], 1)] = v;
    } else {
        int i = gid - N_PTS;
        float x = src[3 * i], y = src[3 * i + 1], z = src[3 * i + 2];
        bool valid = (x != 0.0f) || (y != 0.0f) || (z != 0.0f);
        float s2 = fmaf(x, x, fmaf(y, y, z * z));
        float4 v; v.x = x; v.y = y; v.z = z; v.w = valid ? s2 : -1.0f;
        int c = morton3(cell_coord(x), cell_coord(y), cell_coord(z));
        g_ssort[atomicAdd(&g_scur[c], 1)] = v;
    }
}

// Branchless sorted insert, ascending m0..m4 (exact no-op when q >= m4).
__device__ __forceinline__ void insert5(float q, float& m0, float& m1,
                                        float& m2, float& m3, float& m4) {
    float t0 = fminf(m0, q);
    float t1 = fminf(m1, fmaxf(m0, q));
    float t2 = fminf(m2, fmaxf(m1, q));
    float t3 = fminf(m3, fmaxf(m2, q));
    float t4 = fminf(m4, fmaxf(m3, q));
    m0 = t0; m1 = t1; m2 = t2; m3 = t3; m4 = t4;
}

// Pair (2-lane) merge of ascending-5 lists -> exact union top-5, identical on
// both lanes. One round of the validated butterfly network (xor offset 1).
// MASK = the 2 lanes of this pair; call ONLY at pair-convergent points.
__device__ __forceinline__ void pair_merge5(unsigned pmask,
                                            float& a0, float& a1, float& a2,
                                            float& a3, float& a4) {
    float b0 = __shfl_xor_sync(pmask, a0, 1);
    float b1 = __shfl_xor_sync(pmask, a1, 1);
    float b2 = __shfl_xor_sync(pmask, a2, 1);
    float b3 = __shfl_xor_sync(pmask, a3, 1);
    float b4 = __shfl_xor_sync(pmask, a4, 1);
    float c0 = fminf(a0, b4), c1 = fminf(a1, b3), c2 = fminf(a2, b2);
    float c3 = fminf(a3, b1), c4 = fminf(a4, b0);
    float l04 = fminf(c0, c4), h04 = fmaxf(c0, c4);
    float l13 = fminf(c1, c3), h13 = fmaxf(c1, c3);
    float l2h = fminf(c2, h04), h2h = fmaxf(c2, h04);
    a0 = l04;
    a1 = fminf(l13, l2h); a2 = fmaxf(l13, l2h);
    a3 = fminf(h13, h2h); a4 = fmaxf(h13, h2h);
}

// ---------------------------------------------------------------------------
// Main: TWO TWIN THREADS PER SOURCE. Each twin runs the R12-style scalar
// traversal over its stride-2 candidate subset (control flow pair-uniform;
// NO shfls inside the traversal). Seed = batched 3x3x3 cube; one pair merge
// after seed gives the exact union 5th as starting r2; sphere pass refreshes
// with own m4 (conservative). Candidate loops 2-wide unrolled for MLP.
// 1024 warps -> 2x latency overlap vs R12/R15.
// ---------------------------------------------------------------------------
__global__ __launch_bounds__(MAIN_THREADS)
void knn_main() {
    __shared__ float red_s[MAIN_THREADS / 32];
    __shared__ int   red_c[MAIN_THREADS / 32];

    const int tid  = threadIdx.x;
    const int lane = tid & 31;
    const int warp = tid >> 5;
    const int sub  = tid & 1;
    const unsigned pmask = 0x3u << (lane & ~1);
    const int sid  = blockIdx.x * SRC_PER_BLOCK + (tid >> 1);

    float4 sv = g_ssort[sid];
    const bool  valid = (sv.w >= 0.0f);
    const float sx = sv.x, sy = sv.y, sz = sv.z;
    const float s2 = fmaxf(sv.w, 0.0f);

    float m0 = 1e20f, m1 = 1e20f, m2 = 1e20f, m3 = 1e20f, m4 = 1e20f;

    if (valid) {
        const float px = fminf(fmaxf(sx, XMIN), XMAXV);
        const float py = fminf(fmaxf(sy, XMIN), XMAXV);
        const float pz = fminf(fmaxf(sz, XMIN), XMAXV);
        const int ccx = cell_coord(px);
        const int ccy = cell_coord(py);
        const int ccz = cell_coord(pz);

        int seen = 0;   // TOTAL span candidates (same on both twins)

        // stride-2 candidate scan, 2-wide unrolled (independent loads)
        auto candscan = [&](int st, int en) {
            int i = st + sub;
            for (; i + 2 < en; i += 4) {
                float4 v0 = g_tsort[i];
                float4 v1 = g_tsort[i + 2];
                float q0 = fmaf(sx, v0.x, fmaf(sy, v0.y, fmaf(sz, v0.z, v0.w)));
                float q1 = fmaf(sx, v1.x, fmaf(sy, v1.y, fmaf(sz, v1.z, v1.w)));
                insert5(q0, m0, m1, m2, m3, m4);
                insert5(q1, m0, m1, m2, m3, m4);
            }
            for (; i < en; i += 2) {
                float4 v = g_tsort[i];
                float q = fmaf(sx, v.x, fmaf(sy, v.y, fmaf(sz, v.z, v.w)));
                insert5(q, m0, m1, m2, m3, m4);
            }
        };
        auto spanscan = [&](int cz, int cy, int cxl, int cxr) {
            int base = (cz * NC + cy) * NC;
            int st = g_tstart[base + cxl];
            int en = g_tstart[base + cxr + 1];
            seen += en - st;
            candscan(st, en);
        };

        // ---- seed: radius-1 cube, fully unrolled + batched loads ----
        int rs = 1;
        {
            const int xl = max(ccx - 1, 0), xh = min(ccx + 1, NC - 1);
            unsigned rowm[3];
            int czc[3];
#pragma unroll
            for (int j = 0; j < 3; ++j) {
                int cz = ccz + j - 1;
                czc[j] = min(max(cz, 0), NC - 1);
                rowm[j] = g_rowmask[czc[j]];
            }
            int stA[9], enA[9];
#pragma unroll
            for (int j = 0; j < 9; ++j) {
                const int zj = j / 3, dy = j % 3 - 1;
                const int cz = ccz + zj - 1;
                const int cy = ccy + dy;
                const int cyc = min(max(cy, 0), NC - 1);
                const bool ok = (cz >= 0) && (cz < NC) && (cy >= 0) && (cy < NC)
                              && (((rowm[zj] >> cyc) & 1u) != 0u);
                const int base = (czc[zj] * NC + cyc) * NC;
                int st = g_tstart[base + xl];
                int en = g_tstart[base + xh + 1];
                stA[j] = st;
                enA[j] = ok ? en : st;
            }
            // prefetch this twin's first candidate of every row
            float4 pv[9];
#pragma unroll
            for (int j = 0; j < 9; ++j)
                pv[j] = g_tsort[min(stA[j] + sub, N_PTS - 1)];
#pragma unroll
            for (int j = 0; j < 9; ++j) {
                int st = stA[j], en = enA[j];
                seen += en - st;
                int i = st + sub;
                if (i < en) {
                    float4 v = pv[j];
                    while (true) {
                        float q = fmaf(sx, v.x, fmaf(sy, v.y, fmaf(sz, v.z, v.w)));
                        insert5(q, m0, m1, m2, m3, m4);
                        i += 2;
                        if (i >= en) break;
                        v = g_tsort[i];
                    }
                }
            }
        }

        // rare: expand shells until >=5 TOTAL candidates (pair-uniform)
        while (seen < KNN && rs < NC) {
            ++rs;
            const int zA = ccz - rs, zB = ccz + rs;
            const int yA = ccy - rs, yB = ccy + rs;
            const int xA = ccx - rs, xB = ccx + rs;
            const int xl = max(xA, 0), xr = min(xB, NC - 1);
            for (int cz = max(zA, 0); cz <= min(zB, NC - 1); ++cz) {
                unsigned row = g_rowmask[cz];
                if (!row) continue;
                bool zface = (cz == zA) || (cz == zB);
                for (int cy = max(yA, 0); cy <= min(yB, NC - 1); ++cy) {
                    if (!((row >> cy) & 1u)) continue;
                    if (zface || cy == yA || cy == yB) {
                        spanscan(cz, cy, xl, xr);
                    } else {
                        if (xA >= 0)      spanscan(cz, cy, xA, xA);
                        if (xB <= NC - 1) spanscan(cz, cy, xB, xB);
                    }
                }
            }
        }

        // pair-convergent point: exact union 5th -> tight starting bound
        float r2;
        {
            float a0 = m0, a1 = m1, a2 = m2, a3 = m3, a4 = m4;
            pair_merge5(pmask, a0, a1, a2, a3, a4);
            r2 = a4 + s2;
        }

        // ---- sphere pass minus the seed cube (radius rs); no shfls inside ----
        const int szA = ccz - rs, szB = ccz + rs;
        const int syA = ccy - rs, syB = ccy + rs;
        const int sxA = ccx - rs, sxB = ccx + rs;

        float rmax = sqrtf(r2);
        const int czmin = cell_coord(pz - rmax);
        const int czmax = cell_coord(pz + rmax);

        for (int cz = czmin; cz <= czmax; ++cz) {
            float zcmin = XMIN + cz * W;
            float dz = fmaxf(fmaxf(zcmin - pz, pz - (zcmin + W)), 0.0f);
            float dz2 = dz * dz;
            if (dz2 > r2) continue;
            unsigned row = g_rowmask[cz];
            if (!row) continue;
            float ry = sqrtf(fmaxf(r2 - dz2, 0.0f));
            const int cya = cell_coord(py - ry);
            const int cyb = cell_coord(py + ry);
            const bool zin = (cz >= szA) && (cz <= szB);
            for (int cy = cya; cy <= cyb; ++cy) {
                if (!((row >> cy) & 1u)) continue;
                float ycmin = XMIN + cy * W;
                float dy = fmaxf(fmaxf(ycmin - py, py - (ycmin + W)), 0.0f);
                float dd = fmaf(dy, dy, dz2);
                if (dd > r2) continue;
                float dxm = sqrtf(r2 - dd);
                int axl = cell_coord(px - dxm);
                int axr = cell_coord(px + dxm);
                if (zin && cy >= syA && cy <= syB) {
                    int r1 = min(axr, sxA - 1);
                    if (axl <= r1) spanscan(cz, cy, axl, r1);
                    int l2 = max(axl, sxB + 1);
                    if (l2 <= axr) spanscan(cz, cy, l2, axr);
                } else {
                    spanscan(cz, cy, axl, axr);
                }
                r2 = fminf(r2, m4 + s2);   // own-list refresh (conservative)
            }
        }
    }

    // convergent epilogue: final exact pair merge, then one contribution
    __syncwarp();
    pair_merge5(0x3u << (lane & ~1), m0, m1, m2, m3, m4);

    float sum = 0.0f; int cnt = 0;
    if (valid && sub == 0) {
        sum = sqrtf(fmaxf(m0 + s2, 1e-12f))
            + sqrtf(fmaxf(m1 + s2, 1e-12f))
            + sqrtf(fmaxf(m2 + s2, 1e-12f))
            + sqrtf(fmaxf(m3 + s2, 1e-12f))
            + sqrtf(fmaxf(m4 + s2, 1e-12f));
        cnt = 1;
    }
#pragma unroll
    for (int off = 16; off > 0; off >>= 1) {
        sum += __shfl_xor_sync(0xffffffffu, sum, off);
        cnt += __shfl_xor_sync(0xffffffffu, cnt, off);
    }
    if (lane == 0) { red_s[warp] = sum; red_c[warp] = cnt; }
    __syncthreads();
    if (tid == 0) {
        float bs = 0.0f; int bc = 0;
#pragma unroll
        for (int w = 0; w < MAIN_THREADS / 32; ++w) { bs += red_s[w]; bc += red_c[w]; }
        g_bsum[blockIdx.x] = bs;
        g_bcnt[blockIdx.x] = bc;
    }
}

// ---------------------------------------------------------------------------
__global__ __launch_bounds__(256) void finalize_kernel(float* __restrict__ out) {
    __shared__ double ds[256];
    __shared__ int    di[256];
    int tid = threadIdx.x;
    ds[tid] = (tid < MAIN_BLOCKS) ? (double)g_bsum[tid] : 0.0;
    di[tid] = (tid < MAIN_BLOCKS) ? g_bcnt[tid] : 0;
    __syncthreads();
#pragma unroll
    for (int off = 128; off > 0; off >>= 1) {
        if (tid < off) { ds[tid] += ds[tid + off]; di[tid] += di[tid + off]; }
        __syncthreads();
    }
    if (tid == 0) out[0] = (float)(ds[0] / ((double)di[0] * KNN));
    if (tid < 32) g_flag[tid] = 0;    // reset scan lookback flags for next call
}

// ---------------------------------------------------------------------------
extern "C" void kernel_launch(void* const* d_in, const int* in_sizes, int n_in,
                              void* d_out, int out_size) {
    const float* src = (const float*)d_in[0];  // source_pc (2,8192,3)
    const float* tgt = (const float*)d_in[1];  // target_pc (2,8192,3)
    float* out = (float*)d_out;

    hist_kernel<<<2 * N_PTS / 256, 256>>>(src, tgt);     // launch 0
    scan_kernel<<<32, 1024>>>();                         // launch 1
    scatter_kernel<<<2 * N_PTS / 256, 256>>>(src, tgt);  // launch 2
    knn_main<<<MAIN_BLOCKS, MAIN_THREADS>>>();           // launch 3 (profiled)
    finalize_kernel<<<1, 256>>>(out);                    // launch 4
}

// round 17
// speedup vs baseline: 1.2341x; 1.2341x over previous
#include <cuda_runtime.h>
#include <math.h>

#define N_PTS 16384            // 2*8192 points, both batches flattened
#define KNN 5
#define NC 32                  // cells per axis (3D)
#define NCELLS (NC * NC * NC)  // 32768
#define XMIN (-4.5f)
#define XMAXV (4.5f)
#define W (9.0f / NC)          // 0.28125
#define INV_W (NC / 9.0f)

#define SUBW 4                                   // threads per source (row-split)
#define MAIN_THREADS 128
#define SRC_PER_BLOCK (MAIN_THREADS / SUBW)      // 32
#define MAIN_BLOCKS (N_PTS / SRC_PER_BLOCK)      // 512

// ---- scratch (zero-initialized at module load; re-zeroed in-pipeline) ----
__device__ float4 g_tsort[N_PTS];   // (-2x,-2y,-2z,t^2) cell-ordered (linear z,y,x)
__device__ float4 g_ssort[N_PTS];   // (x,y,z, valid? s2 : -1) Morton-cell-ordered
__device__ int    g_thist[NCELLS];
__device__ int    g_shist[NCELLS];
__device__ int    g_tstart[NCELLS + 1];
__device__ int    g_tcur[NCELLS];
__device__ int    g_scur[NCELLS];
__device__ int    g_pubT[32], g_pubS[32];
__device__ int    g_flag[32];       // scan lookback flags (zeroed by finalize)
__device__ unsigned g_rowmask[NC];  // bit cy of word cz: target row (cz,cy) nonempty
__device__ float  g_bsum[MAIN_BLOCKS];
__device__ int    g_bcnt[MAIN_BLOCKS];

__device__ __forceinline__ int cell_coord(float v) {
    int c = (int)floorf((v - XMIN) * INV_W);
    return min(NC - 1, max(0, c));
}

__device__ __forceinline__ unsigned part1by2(unsigned v) {
    v &= 0x3FF;
    v = (v | (v << 16)) & 0x030000FF;
    v = (v | (v << 8))  & 0x0300F00F;
    v = (v | (v << 4))  & 0x030C30C3;
    v = (v | (v << 2))  & 0x09249249;
    return v;
}
__device__ __forceinline__ int morton3(int cx, int cy, int cz) {
    return (int)(part1by2(cx) | (part1by2(cy) << 1) | (part1by2(cz) << 2));
}

// ---------------------------------------------------------------------------
__global__ void hist_kernel(const float* __restrict__ src,
                            const float* __restrict__ tgt) {
    int gid = blockIdx.x * blockDim.x + threadIdx.x;   // 0..32767
    if (gid < N_PTS) {
        int cx = cell_coord(tgt[3 * gid]);
        int cy = cell_coord(tgt[3 * gid + 1]);
        int cz = cell_coord(tgt[3 * gid + 2]);
        atomicAdd(&g_thist[(cz * NC + cy) * NC + cx], 1);
    } else {
        int i = gid - N_PTS;
        int cx = cell_coord(src[3 * i]);
        int cy = cell_coord(src[3 * i + 1]);
        int cz = cell_coord(src[3 * i + 2]);
        atomicAdd(&g_shist[morton3(cx, cy, cz)], 1);
    }
}

// ---------------------------------------------------------------------------
// scan: ONE kernel, 32 co-resident blocks x 1024 threads, one cell/thread
// (coalesced). Block-local smem scan; cross-block offsets via publish +
// lookback spin. Emits tstart/tcur/scur + rowmask, re-zeroes histograms.
// ---------------------------------------------------------------------------
__global__ __launch_bounds__(1024) void scan_kernel() {
    __shared__ int pt[1024], ps[1024];
    __shared__ int vT[32], vS[32];
    __shared__ unsigned rowocc;
    const int tid = threadIdx.x, b = blockIdx.x;
    const int c = b * 1024 + tid;
    int tv = g_thist[c], sv = g_shist[c];
    if (tid == 0) rowocc = 0u;
    unsigned xbits = __ballot_sync(0xffffffffu, tv > 0);   // warp = one (z,y) row
    __syncthreads();
    if ((tid & 31) == 0 && xbits) atomicOr(&rowocc, 1u << (tid >> 5));
    pt[tid] = tv; ps[tid] = sv;
    __syncthreads();
    for (int off = 1; off < 1024; off <<= 1) {
        int ta = (tid >= off) ? pt[tid - off] : 0;
        int sa = (tid >= off) ? ps[tid - off] : 0;
        __syncthreads();
        pt[tid] += ta; ps[tid] += sa;
        __syncthreads();
    }
    if (tid == 1023) {
        g_pubT[b] = pt[1023];
        g_pubS[b] = ps[1023];
        __threadfence();
        *((volatile int*)&g_flag[b]) = 1;
        g_rowmask[b] = rowocc;          // block b == z-slab b
    }
    if (tid < 32) {
        int t = 0, s = 0;
        if (tid < b) {
            while (*((volatile int*)&g_flag[tid]) == 0) {}
            t = *((volatile int*)&g_pubT[tid]);
            s = *((volatile int*)&g_pubS[tid]);
        }
        vT[tid] = t; vS[tid] = s;
    }
    __syncthreads();
    int bofT = 0, bofS = 0;
    if (tid == 0) {
        for (int i = 0; i < 32; ++i) { bofT += vT[i]; bofS += vS[i]; }
        vT[0] = bofT; vS[0] = bofS;
    }
    __syncthreads();
    bofT = vT[0]; bofS = vS[0];
    int t = pt[tid] - tv + bofT;
    g_tstart[c] = t;  g_tcur[c] = t;
    g_scur[c] = ps[tid] - sv + bofS;
    g_thist[c] = 0;   g_shist[c] = 0;
    if (b == 31 && tid == 1023) g_tstart[NCELLS] = N_PTS;
}

// ---------------------------------------------------------------------------
__global__ void scatter_kernel(const float* __restrict__ src,
                               const float* __restrict__ tgt) {
    int gid = blockIdx.x * blockDim.x + threadIdx.x;
    if (gid < N_PTS) {
        float x = tgt[3 * gid], y = tgt[3 * gid + 1], z = tgt[3 * gid + 2];
        bool valid = (x != 0.0f) || (y != 0.0f) || (z != 0.0f);
        float t2 = fmaf(x, x, fmaf(y, y, z * z));
        float4 v;
        if (valid) { v.x = -2.0f * x; v.y = -2.0f * y; v.z = -2.0f * z; v.w = t2; }
        else       { v.x = 0.0f;      v.y = 0.0f;      v.z = 0.0f;      v.w = 1e30f; }
        int c = (cell_coord(z) * NC + cell_coord(y)) * NC + cell_coord(x);
        g_tsort[atomicAdd(&g_tcur[c], 1)] = v;
    } else {
        int i = gid - N_PTS;
        float x = src[3 * i], y = src[3 * i + 1], z = src[3 * i + 2];
        bool valid = (x != 0.0f) || (y != 0.0f) || (z != 0.0f);
        float s2 = fmaf(x, x, fmaf(y, y, z * z));
        float4 v; v.x = x; v.y = y; v.z = z; v.w = valid ? s2 : -1.0f;
        int c = morton3(cell_coord(x), cell_coord(y), cell_coord(z));
        g_ssort[atomicAdd(&g_scur[c], 1)] = v;
    }
}

// Branchless sorted insert, ascending m0..m4 (exact no-op when q >= m4).
__device__ __forceinline__ void insert5(float q, float& m0, float& m1,
                                        float& m2, float& m3, float& m4) {
    float t0 = fminf(m0, q);
    float t1 = fminf(m1, fmaxf(m0, q));
    float t2 = fminf(m2, fmaxf(m1, q));
    float t3 = fminf(m3, fmaxf(m2, q));
    float t4 = fminf(m4, fmaxf(m3, q));
    m0 = t0; m1 = t1; m2 = t2; m3 = t3; m4 = t4;
}

// Subwarp (4-lane) butterfly merge of ascending-5 lists -> exact union top-5,
// identical on the 4 lanes (validated R14: rel_err = 0). Masked to this
// subwarp; call ONLY at subwarp-convergent points.
__device__ __forceinline__ void sub4_merge5(unsigned smask,
                                            float& a0, float& a1, float& a2,
                                            float& a3, float& a4) {
#pragma unroll
    for (int off = 2; off > 0; off >>= 1) {
        float b0 = __shfl_xor_sync(smask, a0, off);
        float b1 = __shfl_xor_sync(smask, a1, off);
        float b2 = __shfl_xor_sync(smask, a2, off);
        float b3 = __shfl_xor_sync(smask, a3, off);
        float b4 = __shfl_xor_sync(smask, a4, off);
        float c0 = fminf(a0, b4), c1 = fminf(a1, b3), c2 = fminf(a2, b2);
        float c3 = fminf(a3, b1), c4 = fminf(a4, b0);
        float l04 = fminf(c0, c4), h04 = fmaxf(c0, c4);
        float l13 = fminf(c1, c3), h13 = fmaxf(c1, c3);
        float l2h = fminf(c2, h04), h2h = fmaxf(c2, h04);
        a0 = l04;
        a1 = fminf(l13, l2h); a2 = fmaxf(l13, l2h);
        a3 = fminf(h13, h2h); a4 = fmaxf(h13, h2h);
    }
}

// ---------------------------------------------------------------------------
// Main: 4 THREADS PER SOURCE with ROW PARTITIONING. Thread `sub` owns rows
// with (cz+cy)&3 == sub (seed cube: 2-3 of 9 rows; shells; sphere via cy+=4
// stepping). Candidates within an owned row are scanned stride-1. This splits
// BOTH instruction count AND the serial row-setup chain ~4x per thread (R16
// split only candidates -> neutral). NO shfls inside the traversal; subwarp
// syncs only at uniform points: shell-loop head (seen-sum), post-seed merge,
// epilogue merge. 2048 warps for latency overlap.
// ---------------------------------------------------------------------------
__global__ __launch_bounds__(MAIN_THREADS)
void knn_main() {
    __shared__ float red_s[MAIN_THREADS / 32];
    __shared__ int   red_c[MAIN_THREADS / 32];

    const int tid  = threadIdx.x;
    const int lane = tid & 31;
    const int warp = tid >> 5;
    const int sub  = tid & (SUBW - 1);
    const unsigned smask = 0xFu << (lane & ~(SUBW - 1));
    const int sid  = blockIdx.x * SRC_PER_BLOCK + (tid >> 2);

    float4 sv = g_ssort[sid];
    const bool  valid = (sv.w >= 0.0f);
    const float sx = sv.x, sy = sv.y, sz = sv.z;
    const float s2 = fmaxf(sv.w, 0.0f);

    float m0 = 1e20f, m1 = 1e20f, m2 = 1e20f, m3 = 1e20f, m4 = 1e20f;

    if (valid) {   // uniform within the subwarp (shared source)
        const float px = fminf(fmaxf(sx, XMIN), XMAXV);
        const float py = fminf(fmaxf(sy, XMIN), XMAXV);
        const float pz = fminf(fmaxf(sz, XMIN), XMAXV);
        const int ccx = cell_coord(px);
        const int ccy = cell_coord(py);
        const int ccz = cell_coord(pz);

        int seen = 0;   // candidates in MY rows only
        auto candscan = [&](int st, int en) {
            seen += en - st;
            for (int i = st; i < en; ++i) {
                float4 v = g_tsort[i];
                float q = fmaf(sx, v.x, fmaf(sy, v.y, fmaf(sz, v.z, v.w)));
                insert5(q, m0, m1, m2, m3, m4);
            }
        };
        auto spanscan = [&](int cz, int cy, int cxl, int cxr) {
            int base = (cz * NC + cy) * NC;
            int st = g_tstart[base + cxl];
            int en = g_tstart[base + cxr + 1];
            candscan(st, en);
        };

        // ---- seed: radius-1 cube; I scan only my owned rows (batched) ----
        int rs = 1;
        {
            const int xl = max(ccx - 1, 0), xh = min(ccx + 1, NC - 1);
            unsigned rowm[3];
            int czc[3];
#pragma unroll
            for (int j = 0; j < 3; ++j) {
                int cz = ccz + j - 1;
                czc[j] = min(max(cz, 0), NC - 1);
                rowm[j] = g_rowmask[czc[j]];
            }
            int stA[9], enA[9];
#pragma unroll
            for (int j = 0; j < 9; ++j) {
                const int zj = j / 3, dy = j % 3 - 1;
                const int cz = ccz + zj - 1;
                const int cy = ccy + dy;
                const int cyc = min(max(cy, 0), NC - 1);
                const bool ok = (cz >= 0) && (cz < NC) && (cy >= 0) && (cy < NC)
                              && (((rowm[zj] >> cyc) & 1u) != 0u)
                              && (((cz + cy) & 3) == sub);     // row ownership
                const int base = (czc[zj] * NC + cyc) * NC;
                int st = g_tstart[base + xl];
                int en = g_tstart[base + xh + 1];
                stA[j] = st;
                enA[j] = ok ? en : st;
            }
            float4 pv[9];
#pragma unroll
            for (int j = 0; j < 9; ++j)
                pv[j] = g_tsort[min(stA[j], N_PTS - 1)];
#pragma unroll
            for (int j = 0; j < 9; ++j) {
                int st = stA[j], en = enA[j];
                seen += en - st;
                if (st < en) {
                    float4 v = pv[j];
                    int i = st;
                    while (true) {
                        float q = fmaf(sx, v.x, fmaf(sy, v.y, fmaf(sz, v.z, v.w)));
                        insert5(q, m0, m1, m2, m3, m4);
                        if (++i >= en) break;
                        v = g_tsort[i];
                    }
                }
            }
        }

        // shell expansion until the UNION has >=5 candidates (rare).
        // Loop condition is subwarp-uniform (shfl-summed seen); the shfls sit
        // at subwarp-convergent points (R14-validated masked pattern).
        while (rs < NC) {
            int tot = seen;
            tot += __shfl_xor_sync(smask, tot, 1);
            tot += __shfl_xor_sync(smask, tot, 2);
            if (tot >= KNN) break;
            ++rs;
            const int zA = ccz - rs, zB = ccz + rs;
            const int yA = ccy - rs, yB = ccy + rs;
            const int xA = ccx - rs, xB = ccx + rs;
            const int xl = max(xA, 0), xr = min(xB, NC - 1);
            for (int cz = max(zA, 0); cz <= min(zB, NC - 1); ++cz) {
                unsigned row = g_rowmask[cz];
                if (!row) continue;
                bool zface = (cz == zA) || (cz == zB);
                for (int cy = max(yA, 0); cy <= min(yB, NC - 1); ++cy) {
                    if (((cz + cy) & 3) != sub) continue;      // row ownership
                    if (!((row >> cy) & 1u)) continue;
                    if (zface || cy == yA || cy == yB) {
                        spanscan(cz, cy, xl, xr);
                    } else {
                        if (xA >= 0)      spanscan(cz, cy, xA, xA);
                        if (xB <= NC - 1) spanscan(cz, cy, xB, xB);
                    }
                }
            }
        }

        // subwarp-convergent point: exact union 5th -> tight starting bound
        float r2;
        {
            float a0 = m0, a1 = m1, a2 = m2, a3 = m3, a4 = m4;
            sub4_merge5(smask, a0, a1, a2, a3, a4);
            r2 = a4 + s2;
        }

        // ---- sphere pass minus the seed cube; my rows only (cy += 4) ----
        const int szA = ccz - rs, szB = ccz + rs;
        const int syA = ccy - rs, syB = ccy + rs;
        const int sxA = ccx - rs, sxB = ccx + rs;

        float rmax = sqrtf(r2);
        const int czmin = cell_coord(pz - rmax);
        const int czmax = cell_coord(pz + rmax);

        for (int cz = czmin; cz <= czmax; ++cz) {
            float zcmin = XMIN + cz * W;
            float dz = fmaxf(fmaxf(zcmin - pz, pz - (zcmin + W)), 0.0f);
            float dz2 = dz * dz;
            if (dz2 > r2) continue;
            unsigned row = g_rowmask[cz];
            if (!row) continue;
            float ry = sqrtf(fmaxf(r2 - dz2, 0.0f));
            const int cya = cell_coord(py - ry);
            const int cyb = cell_coord(py + ry);
            const bool zin = (cz >= szA) && (cz <= szB);
            // first cy >= cya with (cz+cy)&3 == sub
            int cy = cya + ((sub - cz - cya) & 3);
            for (; cy <= cyb; cy += 4) {
                if (!((row >> cy) & 1u)) continue;
                float ycmin = XMIN + cy * W;
                float dy = fmaxf(fmaxf(ycmin - py, py - (ycmin + W)), 0.0f);
                float dd = fmaf(dy, dy, dz2);
                if (dd > r2) continue;
                float dxm = sqrtf(r2 - dd);
                int axl = cell_coord(px - dxm);
                int axr = cell_coord(px + dxm);
                if (zin && cy >= syA && cy <= syB) {
                    int r1 = min(axr, sxA - 1);
                    if (axl <= r1) spanscan(cz, cy, axl, r1);
                    int l2 = max(axl, sxB + 1);
                    if (l2 <= axr) spanscan(cz, cy, l2, axr);
                } else {
                    spanscan(cz, cy, axl, axr);
                }
                r2 = fminf(r2, m4 + s2);   // own-list refresh (conservative)
            }
        }
    }

    // convergent epilogue: final exact subwarp merge, then one contribution
    __syncwarp();
    sub4_merge5(smask, m0, m1, m2, m3, m4);

    float sum = 0.0f; int cnt = 0;
    if (valid && sub == 0) {
        sum = sqrtf(fmaxf(m0 + s2, 1e-12f))
            + sqrtf(fmaxf(m1 + s2, 1e-12f))
            + sqrtf(fmaxf(m2 + s2, 1e-12f))
            + sqrtf(fmaxf(m3 + s2, 1e-12f))
            + sqrtf(fmaxf(m4 + s2, 1e-12f));
        cnt = 1;
    }
#pragma unroll
    for (int off = 16; off > 0; off >>= 1) {
        sum += __shfl_xor_sync(0xffffffffu, sum, off);
        cnt += __shfl_xor_sync(0xffffffffu, cnt, off);
    }
    if (lane == 0) { red_s[warp] = sum; red_c[warp] = cnt; }
    __syncthreads();
    if (tid == 0) {
        float bs = 0.0f; int bc = 0;
#pragma unroll
        for (int w = 0; w < MAIN_THREADS / 32; ++w) { bs += red_s[w]; bc += red_c[w]; }
        g_bsum[blockIdx.x] = bs;
        g_bcnt[blockIdx.x] = bc;
    }
}

// ---------------------------------------------------------------------------
__global__ __launch_bounds__(512) void finalize_kernel(float* __restrict__ out) {
    __shared__ double ds[512];
    __shared__ int    di[512];
    int tid = threadIdx.x;
    ds[tid] = (double)g_bsum[tid];
    di[tid] = g_bcnt[tid];
    __syncthreads();
#pragma unroll
    for (int off = 256; off > 0; off >>= 1) {
        if (tid < off) { ds[tid] += ds[tid + off]; di[tid] += di[tid + off]; }
        __syncthreads();
    }
    if (tid == 0) out[0] = (float)(ds[0] / ((double)di[0] * KNN));
    if (tid < 32) g_flag[tid] = 0;    // reset scan lookback flags for next call
}

// ---------------------------------------------------------------------------
extern "C" void kernel_launch(void* const* d_in, const int* in_sizes, int n_in,
                              void* d_out, int out_size) {
    const float* src = (const float*)d_in[0];  // source_pc (2,8192,3)
    const float* tgt = (const float*)d_in[1];  // target_pc (2,8192,3)
    float* out = (float*)d_out;

    hist_kernel<<<2 * N_PTS / 256, 256>>>(src, tgt);     // launch 0
    scan_kernel<<<32, 1024>>>();                         // launch 1
    scatter_kernel<<<2 * N_PTS / 256, 256>>>(src, tgt);  // launch 2
    knn_main<<<MAIN_BLOCKS, MAIN_THREADS>>>();           // launch 3 (profiled)
    finalize_kernel<<<1, 512>>>(out);                    // launch 4
}